// round 7
// baseline (speedup 1.0000x reference)
#include <cuda_runtime.h>

#define D 64
#define L 64
#define BB 8
#define MAT (D*D)          // 4096 floats per matrix
#define NMAT (BB*L)        // 512 matrices
#define PA 68              // padded smem pitch for A (kills bank conflicts)

typedef unsigned long long u64;

// All matrices in reciprocal-exp domain: W = exp(-m).
// log-semiring matmul:  out[i,j] = rcp( sum_k rcp( A[i,k] + B[k,j] ) )
__device__ float g_buf0[NMAT * MAT];   // 8MB
__device__ float g_buf1[NMAT * MAT];   // 8MB
__device__ float g_wtab[4 * MAT];      // exp(-p[a+1])
__device__ float g_ttab[16 * MAT];     // pair products  W(a) (x) W(b)
__device__ float g_qtab[256 * MAT];    // quad products  pair (x) pair
__device__ float g_p0tab[MAT];         // exp(-p[0])

__device__ __forceinline__ float frcp(float x) {
    float r;
    asm("rcp.approx.f32 %0, %1;" : "=f"(r) : "f"(x));
    return r;
}

// Split-statement f32x2 helpers: each op is its own asm so ptxas regalloc can
// elide the pack/unpack movs by assigning scalars to aligned register pairs.
__device__ __forceinline__ u64 pack2(float lo, float hi) {
    u64 r;
    asm("mov.b64 %0, {%1, %2};" : "=l"(r) : "f"(lo), "f"(hi));
    return r;
}
__device__ __forceinline__ u64 bcast2(float v) {
    u64 r;
    asm("mov.b64 %0, {%1, %1};" : "=l"(r) : "f"(v));
    return r;
}
__device__ __forceinline__ void unpack2(u64 v, float& lo, float& hi) {
    asm("mov.b64 {%0, %1}, %2;" : "=f"(lo), "=f"(hi) : "l"(v));
}
__device__ __forceinline__ u64 addx2(u64 a, u64 b) {
    u64 r;
    asm("add.rn.f32x2 %0, %1, %2;" : "=l"(r) : "l"(a), "l"(b));
    return r;
}

// One k-step for 4 output columns:
//   acc01 += {rcp(a+b0), rcp(a+b1)};  acc23 += {rcp(a+b2), rcp(a+b3)}
__device__ __forceinline__ void kstep(float a, u64 b01, u64 b23,
                                      u64& acc01, u64& acc23) {
    u64 aa = bcast2(a);
    u64 s01 = addx2(aa, b01);
    u64 s23 = addx2(aa, b23);
    float s0, s1, s2, s3;
    unpack2(s01, s0, s1);
    unpack2(s23, s2, s3);
    u64 r01 = pack2(frcp(s0), frcp(s1));
    u64 r23 = pack2(frcp(s2), frcp(s3));
    acc01 = addx2(acc01, r01);
    acc23 = addx2(acc23, r23);
}

// ---------------------------------------------------------------------------
// Quarter matmul: one CTA computes a 64x16 column slice (quarter q) of
// Dst = A (x) B.   256 threads, thread = (row, colgroup of 4).
// ---------------------------------------------------------------------------
__device__ __forceinline__ void mm_quarter(const float* __restrict__ A,
                                           const float* __restrict__ B,
                                           float* __restrict__ Dst, int q) {
    __shared__ float sA[D * PA];       // full A, padded pitch
    __shared__ float sB[D * 16];       // quarter of B
    const int t = threadIdx.x;

    // stage A (4 float4 per thread)
#pragma unroll
    for (int i = 0; i < 4; i++) {
        int idx = t + i * 256;          // float4 index 0..1023
        int r = idx >> 4, c = idx & 15;
        *(float4*)&sA[r * PA + c * 4] = ((const float4*)A)[idx];
    }
    // stage B quarter (1 float4 per thread)
    {
        int k = t >> 2, g = t & 3;
        *(float4*)&sB[k * 16 + g * 4] = *(const float4*)&B[k * D + q * 16 + g * 4];
    }
    __syncthreads();

    const int row = t >> 2, cg = t & 3;
    const float* ap = &sA[row * PA];
    const float* bp = &sB[cg * 4];
    u64 acc01 = 0ull, acc23 = 0ull;    // (0.f, 0.f) bit patterns
#pragma unroll
    for (int k4 = 0; k4 < 16; k4++) {
        float4 av = *(const float4*)&ap[k4 * 4];
        ulonglong2 b0 = *(const ulonglong2*)&bp[(k4 * 4 + 0) * 16];
        ulonglong2 b1 = *(const ulonglong2*)&bp[(k4 * 4 + 1) * 16];
        ulonglong2 b2 = *(const ulonglong2*)&bp[(k4 * 4 + 2) * 16];
        ulonglong2 b3 = *(const ulonglong2*)&bp[(k4 * 4 + 3) * 16];
        kstep(av.x, b0.x, b0.y, acc01, acc23);
        kstep(av.y, b1.x, b1.y, acc01, acc23);
        kstep(av.z, b2.x, b2.y, acc01, acc23);
        kstep(av.w, b3.x, b3.y, acc01, acc23);
    }
    float s0, s1, s2, s3;
    unpack2(acc01, s0, s1);
    unpack2(acc23, s2, s3);
    *(float4*)&Dst[row * D + q * 16 + cg * 4] =
        make_float4(frcp(s0), frcp(s1), frcp(s2), frcp(s3));
}

// ---------------------------------------------------------------------------
// "Latest value" resolver: where does value of index m live before pass 2^slog?
// ---------------------------------------------------------------------------
__device__ __forceinline__ const float* latest(const int* __restrict__ act,
                                               int b, int m, int slog) {
    size_t off = (size_t)(b * L + m) * MAT;
    if (m < 2) return g_buf0 + off;
    int p = 31 - __clz(m);
    if (p > slog - 1) p = slog - 1;
    if (p == 1) {
        if (m == 2) return g_buf1 + off;
        const int* a = act + b * L + (m - 3);
        int idx = ((a[0] * 4 + a[1]) * 4 + a[2]) * 4 + a[3];
        return g_qtab + (size_t)idx * MAT;
    }
    return (p & 1) ? g_buf1 + off : g_buf0 + off;
}

// ---------------------------------------------------------------------------
// Kernels
// ---------------------------------------------------------------------------
__global__ void exp_tab_kernel(const float* __restrict__ p) {
    int a = blockIdx.x;
    const float4* src = (const float4*)(p + (size_t)a * MAT);
    float4* dst = (a == 0) ? (float4*)g_p0tab
                           : (float4*)(g_wtab + (size_t)(a - 1) * MAT);
    for (int i = threadIdx.x; i < MAT / 4; i += 256) {
        float4 v = src[i];
        dst[i] = make_float4(expf(-v.x), expf(-v.y), expf(-v.z), expf(-v.w));
    }
}

// 16 pair products, 4 quarters each = 64 CTAs
__global__ void __launch_bounds__(256, 5) pair_kernel() {
    int pidx = blockIdx.x >> 2, q = blockIdx.x & 3;
    int a = pidx >> 2, b = pidx & 3;
    mm_quarter(g_wtab + (size_t)a * MAT, g_wtab + (size_t)b * MAT,
               g_ttab + (size_t)pidx * MAT, q);
}

// quads (1024) + tris (32) + step-1 copies for l=0,1 (16) = 1072 CTAs
__global__ void __launch_bounds__(256, 5) stage2_kernel(const int* __restrict__ act) {
    int bid = blockIdx.x;
    if (bid < 1024) {
        int qidx = bid >> 2, q = bid & 3;
        mm_quarter(g_ttab + (size_t)(qidx >> 4) * MAT,
                   g_ttab + (size_t)(qidx & 15) * MAT,
                   g_qtab + (size_t)qidx * MAT, q);
    } else if (bid < 1056) {
        int i = bid - 1024;
        int b = i >> 2, q = i & 3;
        int a0 = act[b * L], a12 = act[b * L + 1] * 4 + act[b * L + 2];
        mm_quarter(g_wtab + (size_t)a0 * MAT, g_ttab + (size_t)a12 * MAT,
                   g_buf1 + (size_t)(b * L + 2) * MAT, q);
    } else {
        int i = bid - 1056;                 // 0..15
        int b = i >> 1, which = i & 1;      // l = 0 or 1
        const float* src = which
            ? g_ttab + (size_t)(act[b * L] * 4 + act[b * L + 1]) * MAT
            : g_wtab + (size_t)act[b * L] * MAT;
        float* dst = g_buf0 + (size_t)(b * L + which) * MAT;
        for (int j = threadIdx.x; j < MAT / 4; j += 256)
            ((float4*)dst)[j] = ((const float4*)src)[j];
    }
}

// Doubling pass for step = 2^slog (slog >= 2). No copies; writes only l >= step.
__global__ void __launch_bounds__(256, 5) step_kernel(const int* __restrict__ act,
                                                      int slog) {
    int step = 1 << slog;
    int n = L - step;
    int idx = blockIdx.x >> 2, q = blockIdx.x & 3;
    int b = idx / n;
    int l = step + (idx - b * n);
    const float* A = latest(act, b, l - step, slog);
    const float* Bm = latest(act, b, l, slog);
    float* dstbuf = (slog & 1) ? g_buf1 : g_buf0;
    mm_quarter(A, Bm, dstbuf + (size_t)(b * L + l) * MAT, q);
}

// Final: x = init (x) PM ; y = x (x) p0 ; output in log domain.
__global__ void final_kernel(const int* __restrict__ act,
                             const float* __restrict__ init_vec,
                             float* __restrict__ out) {
    int bl = blockIdx.x;
    int b = bl >> 6, l = bl & 63;
    const float* W = latest(act, b, l, 6);
    __shared__ float ci[D];
    __shared__ float xw[D];
    int t = threadIdx.x;                   // 64 threads
    ci[t] = expf(-init_vec[t]);
    __syncthreads();

    float s = 0.f;
#pragma unroll 8
    for (int k = 0; k < D; k++)
        s += frcp(ci[k] + W[k * D + t]);
    xw[t] = frcp(s);
    __syncthreads();

    float s2 = 0.f;
#pragma unroll 8
    for (int k = 0; k < D; k++)
        s2 += frcp(xw[k] + g_p0tab[k * D + t]);
    out[(size_t)bl * D + t] = logf(s2);
}

extern "C" void kernel_launch(void* const* d_in, const int* in_sizes, int n_in,
                              void* d_out, int out_size) {
    const float* p        = (const float*)d_in[0];  // (5, 64, 64)
    const float* init_vec = (const float*)d_in[1];  // (64,)
    const int*   act      = (const int*)d_in[2];    // (8, 64)
    float* out = (float*)d_out;                     // (8, 64, 64)

    exp_tab_kernel<<<5, 256>>>(p);
    pair_kernel<<<64, 256>>>();
    stage2_kernel<<<1072, 256>>>(act);
    step_kernel<<<8 * (L - 4)  * 4, 256>>>(act, 2);   // 1920 CTAs -> buf0
    step_kernel<<<8 * (L - 8)  * 4, 256>>>(act, 3);   // 1792 CTAs -> buf1
    step_kernel<<<8 * (L - 16) * 4, 256>>>(act, 4);   // 1536 CTAs -> buf0
    step_kernel<<<8 * (L - 32) * 4, 256>>>(act, 5);   // 1024 CTAs -> buf1
    final_kernel<<<512, 64>>>(act, init_vec, out);
}

// round 8
// speedup vs baseline: 1.0989x; 1.0989x over previous
#include <cuda_runtime.h>
#include <cuda_fp16.h>

#define D 64
#define L 64
#define BB 8
#define MAT (D*D)          // 4096 elems per matrix
#define NMAT (BB*L)        // 512 matrices
#define PA 68              // fp32 A pitch (floats)
#define PAH 72             // fp16 A pitch (halves) -> 144B rows, conflict-free

// All matrices in reciprocal-exp domain: W = exp(-m).
// log-semiring matmul:  out[i,j] = rcp( sum_k rcp( A[i,k] + B[k,j] ) )
// fp16 path: matrices stored normalized (max=1) with fp32 scale; matmul uses
// common scale s = max(sA,sB), rescales the smaller operand during staging.
__device__ float g_buf0[NMAT * MAT];   // fp32 raw outputs (normalized units)
__device__ float g_buf1[NMAT * MAT];
__device__ float g_presc0[NMAT];       // scale of raw values in buf0/buf1
__device__ float g_presc1[NMAT];
__device__ float g_wtab[4 * MAT];      // exp(-p[a+1]) true fp32
__device__ float g_ttab[16 * MAT];     // pair products, true fp32
__device__ float g_qtab[256 * MAT];    // quad products, true fp32
__device__ float g_p0tab[MAT];         // exp(-p[0])

// fp16 normalized mirrors (+ per-matrix scales). uint4 storage for alignment.
__device__ uint4 h_buf0_[NMAT * MAT / 8];
__device__ uint4 h_buf1_[NMAT * MAT / 8];
__device__ uint4 h_qtab_[256 * MAT / 8];
__device__ float sc_buf0[NMAT];
__device__ float sc_buf1[NMAT];
__device__ float sc_qtab[256];
#define H_BUF0 ((__half*)h_buf0_)
#define H_BUF1 ((__half*)h_buf1_)
#define H_QTAB ((__half*)h_qtab_)

__device__ __forceinline__ float frcp(float x) {
    float r;
    asm("rcp.approx.f32 %0, %1;" : "=f"(r) : "f"(x));
    return r;
}

// ---------------------------------------------------------------------------
// fp32 quarter matmul (used for pair/stage2 tables — 15% of the work).
// ---------------------------------------------------------------------------
__device__ __forceinline__ void mm_quarter(const float* __restrict__ A,
                                           const float* __restrict__ B,
                                           float* __restrict__ Dst, int q) {
    __shared__ float sA[D * PA];
    __shared__ float sB[D * 16];
    const int t = threadIdx.x;
#pragma unroll
    for (int i = 0; i < 4; i++) {
        int idx = t + i * 256;
        int r = idx >> 4, c = idx & 15;
        *(float4*)&sA[r * PA + c * 4] = ((const float4*)A)[idx];
    }
    {
        int k = t >> 2, g = t & 3;
        *(float4*)&sB[k * 16 + g * 4] = *(const float4*)&B[k * D + q * 16 + g * 4];
    }
    __syncthreads();

    const int row = t >> 2, cg = t & 3;
    const float* ap = &sA[row * PA];
    const float* bp = &sB[cg * 4];
    float a0 = 0.f, a1 = 0.f, a2 = 0.f, a3 = 0.f;
#pragma unroll
    for (int k4 = 0; k4 < 16; k4++) {
        float4 av = *(const float4*)&ap[k4 * 4];
        float4 bA = *(const float4*)&bp[(k4 * 4 + 0) * 16];
        float4 bB = *(const float4*)&bp[(k4 * 4 + 1) * 16];
        float4 bC = *(const float4*)&bp[(k4 * 4 + 2) * 16];
        float4 bD = *(const float4*)&bp[(k4 * 4 + 3) * 16];
        a0 += frcp(av.x + bA.x); a1 += frcp(av.x + bA.y);
        a2 += frcp(av.x + bA.z); a3 += frcp(av.x + bA.w);
        a0 += frcp(av.y + bB.x); a1 += frcp(av.y + bB.y);
        a2 += frcp(av.y + bB.z); a3 += frcp(av.y + bB.w);
        a0 += frcp(av.z + bC.x); a1 += frcp(av.z + bC.y);
        a2 += frcp(av.z + bC.z); a3 += frcp(av.z + bC.w);
        a0 += frcp(av.w + bD.x); a1 += frcp(av.w + bD.y);
        a2 += frcp(av.w + bD.z); a3 += frcp(av.w + bD.w);
    }
    *(float4*)&Dst[row * D + q * 16 + cg * 4] =
        make_float4(frcp(a0), frcp(a1), frcp(a2), frcp(a3));
}

// ---------------------------------------------------------------------------
// Resolvers. Value of index m before pass 2^slog lives at level
// p = min(floor(log2 m), slog-1):  p=0 -> buf0 singles/pairs; p=1 -> tri (m==2)
// in buf1 or quad table; p even -> buf0, p odd -> buf1.
// ---------------------------------------------------------------------------
struct HMat { const __half* m; float sc; };
struct RMat { const float* m; float sc; };

__device__ __forceinline__ int quad_idx(const int* __restrict__ act, int b, int m) {
    const int* a = act + b * L + (m - 3);
    return ((a[0] * 4 + a[1]) * 4 + a[2]) * 4 + a[3];
}

__device__ __forceinline__ HMat latest_h(const int* __restrict__ act,
                                         int b, int m, int slog) {
    int slot = b * L + m;
    size_t off = (size_t)slot * MAT;
    HMat r;
    if (m < 2) { r.m = H_BUF0 + off; r.sc = sc_buf0[slot]; return r; }
    int p = 31 - __clz(m);
    if (p > slog - 1) p = slog - 1;
    if (p == 1) {
        if (m == 2) { r.m = H_BUF1 + off; r.sc = sc_buf1[slot]; return r; }
        int idx = quad_idx(act, b, m);
        r.m = H_QTAB + (size_t)idx * MAT; r.sc = sc_qtab[idx]; return r;
    }
    if (p & 1) { r.m = H_BUF1 + off; r.sc = sc_buf1[slot]; }
    else       { r.m = H_BUF0 + off; r.sc = sc_buf0[slot]; }
    return r;
}

__device__ __forceinline__ RMat latest_raw(const int* __restrict__ act,
                                           int b, int m) {   // slog = 6
    int slot = b * L + m;
    size_t off = (size_t)slot * MAT;
    RMat r;
    if (m < 2) { r.m = g_buf0 + off; r.sc = 1.f; return r; }
    int p = 31 - __clz(m);
    if (p > 5) p = 5;
    if (p == 1) {
        if (m == 2) { r.m = g_buf1 + off; r.sc = 1.f; return r; }
        int idx = quad_idx(act, b, m);
        r.m = g_qtab + (size_t)idx * MAT; r.sc = 1.f; return r;
    }
    if (p & 1) { r.m = g_buf1 + off; r.sc = g_presc1[slot]; }
    else       { r.m = g_buf0 + off; r.sc = g_presc0[slot]; }
    return r;
}

// ---------------------------------------------------------------------------
// exp tables
// ---------------------------------------------------------------------------
__global__ void exp_tab_kernel(const float* __restrict__ p) {
    int a = blockIdx.x;
    const float4* src = (const float4*)(p + (size_t)a * MAT);
    float4* dst = (a == 0) ? (float4*)g_p0tab
                           : (float4*)(g_wtab + (size_t)(a - 1) * MAT);
    for (int i = threadIdx.x; i < MAT / 4; i += 256) {
        float4 v = src[i];
        dst[i] = make_float4(expf(-v.x), expf(-v.y), expf(-v.z), expf(-v.w));
    }
}

// ---------------------------------------------------------------------------
// fp32 table stages (pair products, quads, tris, base copies)
// ---------------------------------------------------------------------------
__global__ void __launch_bounds__(256, 5) pair_kernel() {
    int pidx = blockIdx.x >> 2, q = blockIdx.x & 3;
    int a = pidx >> 2, b = pidx & 3;
    mm_quarter(g_wtab + (size_t)a * MAT, g_wtab + (size_t)b * MAT,
               g_ttab + (size_t)pidx * MAT, q);
}

__global__ void __launch_bounds__(256, 5) stage2_kernel(const int* __restrict__ act) {
    int bid = blockIdx.x;
    if (bid < 1024) {
        int qidx = bid >> 2, q = bid & 3;
        mm_quarter(g_ttab + (size_t)(qidx >> 4) * MAT,
                   g_ttab + (size_t)(qidx & 15) * MAT,
                   g_qtab + (size_t)qidx * MAT, q);
    } else if (bid < 1056) {
        int i = bid - 1024;
        int b = i >> 2, q = i & 3;
        int a0 = act[b * L], a12 = act[b * L + 1] * 4 + act[b * L + 2];
        mm_quarter(g_wtab + (size_t)a0 * MAT, g_ttab + (size_t)a12 * MAT,
                   g_buf1 + (size_t)(b * L + 2) * MAT, q);
    } else {
        int i = bid - 1056;
        int b = i >> 1, which = i & 1;
        const float* src = which
            ? g_ttab + (size_t)(act[b * L] * 4 + act[b * L + 1]) * MAT
            : g_wtab + (size_t)act[b * L] * MAT;
        float* dst = g_buf0 + (size_t)(b * L + which) * MAT;
        for (int j = threadIdx.x; j < MAT / 4; j += 256)
            ((float4*)dst)[j] = ((const float4*)src)[j];
    }
}

// ---------------------------------------------------------------------------
// Convert: fp32 (normalized-units raw, scale presc) -> fp16 max-normalized + sc.
// 128 threads per matrix.
// ---------------------------------------------------------------------------
__device__ __forceinline__ void conv_core(const float* __restrict__ src,
                                          __half* __restrict__ dst,
                                          float presc, float* __restrict__ sc_out) {
    __shared__ float wmax[4];
    int t = threadIdx.x;   // 128
    float4 v[8];
    float m = 0.f;
#pragma unroll
    for (int i = 0; i < 8; i++) {
        v[i] = ((const float4*)src)[t + i * 128];
        m = fmaxf(m, fmaxf(fmaxf(v[i].x, v[i].y), fmaxf(v[i].z, v[i].w)));
    }
#pragma unroll
    for (int o = 16; o; o >>= 1) m = fmaxf(m, __shfl_xor_sync(0xffffffffu, m, o));
    if ((t & 31) == 0) wmax[t >> 5] = m;
    __syncthreads();
    float mx = fmaxf(fmaxf(wmax[0], wmax[1]), fmaxf(wmax[2], wmax[3]));
    float inv = (mx > 0.f) ? 1.f / mx : 0.f;
#pragma unroll
    for (int i = 0; i < 8; i++) {
        __half2 h0 = __floats2half2_rn(v[i].x * inv, v[i].y * inv);
        __half2 h1 = __floats2half2_rn(v[i].z * inv, v[i].w * inv);
        uint2 u;
        u.x = *(unsigned*)&h0;
        u.y = *(unsigned*)&h1;
        ((uint2*)dst)[t + i * 128] = u;
    }
    if (t == 0) *sc_out = presc * mx;
}

// Initial converts: 256 quads + 8 tris + 16 base (l=0,1) = 280 matrices.
__global__ void conv_init_kernel() {
    int bid = blockIdx.x;
    if (bid < 256) {
        conv_core(g_qtab + (size_t)bid * MAT, H_QTAB + (size_t)bid * MAT,
                  1.f, &sc_qtab[bid]);
    } else if (bid < 264) {
        int b = bid - 256;
        int slot = b * L + 2;
        conv_core(g_buf1 + (size_t)slot * MAT, H_BUF1 + (size_t)slot * MAT,
                  1.f, &sc_buf1[slot]);
        if (threadIdx.x == 0) g_presc1[slot] = 1.f;
    } else {
        int i = bid - 264;
        int b = i >> 1, which = i & 1;
        int slot = b * L + which;
        conv_core(g_buf0 + (size_t)slot * MAT, H_BUF0 + (size_t)slot * MAT,
                  1.f, &sc_buf0[slot]);
        if (threadIdx.x == 0) g_presc0[slot] = 1.f;
    }
}

// Per-pass converts: the just-written (b, l >= step) matrices.
__global__ void conv_pass_kernel(int slog) {
    int step = 1 << slog, n = L - step;
    int b = blockIdx.x / n;
    int l = step + (blockIdx.x - b * n);
    int slot = b * L + l;
    const float* src = ((slog & 1) ? g_buf1 : g_buf0) + (size_t)slot * MAT;
    __half* dst = ((slog & 1) ? H_BUF1 : H_BUF0) + (size_t)slot * MAT;
    float presc = ((slog & 1) ? g_presc1 : g_presc0)[slot];
    float* sc = ((slog & 1) ? sc_buf1 : sc_buf0) + slot;
    conv_core(src, dst, presc, sc);
}

// ---------------------------------------------------------------------------
// fp16 quarter matmul doubling pass. Inner math: HADD2 + h2rcp (2 elems/MUFU).
// 8 interleaved fp16x2 partial accumulators, merged in fp32.
// ---------------------------------------------------------------------------
__global__ void __launch_bounds__(256, 5) hstep_kernel(const int* __restrict__ act,
                                                       int slog) {
    int step = 1 << slog, n = L - step;
    int idx = blockIdx.x >> 2, q = blockIdx.x & 3;
    int b = idx / n;
    int l = step + (idx - b * n);
    HMat A = latest_h(act, b, l - step, slog);
    HMat Bm = latest_h(act, b, l, slog);
    float s = fmaxf(A.sc, Bm.sc);
    __half2 rA = __float2half2_rn(A.sc / s);   // exactly 1.0 for the larger side
    __half2 rB = __float2half2_rn(Bm.sc / s);

    __shared__ __align__(16) __half sA[D * PAH];
    __shared__ __align__(16) __half sB[D * 16];
    const int t = threadIdx.x;

    // stage A: 4096 halves = 512 x (8 halves); rescale by rA
#pragma unroll
    for (int i = 0; i < 2; i++) {
        int id = t + i * 256;
        int r = id >> 3, c8 = id & 7;
        uint4 v = ((const uint4*)A.m)[id];
        __half2* hv = (__half2*)&v;
        hv[0] = __hmul2(hv[0], rA); hv[1] = __hmul2(hv[1], rA);
        hv[2] = __hmul2(hv[2], rA); hv[3] = __hmul2(hv[3], rA);
        *(uint4*)&sA[r * PAH + c8 * 8] = v;
    }
    // stage B quarter: 64 rows x 16 halves = 128 x (8 halves); rescale by rB
    if (t < 128) {
        int r = t >> 1, c8 = t & 1;
        uint4 v = *(const uint4*)&Bm.m[r * D + q * 16 + c8 * 8];
        __half2* hv = (__half2*)&v;
        hv[0] = __hmul2(hv[0], rB); hv[1] = __hmul2(hv[1], rB);
        hv[2] = __hmul2(hv[2], rB); hv[3] = __hmul2(hv[3], rB);
        *(uint4*)&sB[r * 16 + c8 * 8] = v;
    }
    __syncthreads();

    const int row = t >> 2, cg = t & 3;
    const __half* ap = &sA[row * PAH];
    const __half* bp = &sB[cg * 4];
    const __half2 hz = __float2half2_rn(0.f);
    __half2 acc01[8], acc23[8];
#pragma unroll
    for (int i = 0; i < 8; i++) { acc01[i] = hz; acc23[i] = hz; }

#pragma unroll
    for (int k8 = 0; k8 < 8; k8++) {
        uint4 a8 = *(const uint4*)&ap[k8 * 8];
        const __half2* ah = (const __half2*)&a8;
#pragma unroll
        for (int kk = 0; kk < 4; kk++) {
            int k0 = k8 * 8 + kk * 2;
            __half2 alo = __low2half2(ah[kk]);
            __half2 ahi = __high2half2(ah[kk]);
            int pi = kk * 2;
            uint2 b0 = *(const uint2*)&bp[k0 * 16];
            __half2 b01 = *(__half2*)&b0.x, b23 = *(__half2*)&b0.y;
            acc01[pi] = __hadd2(acc01[pi], h2rcp(__hadd2(alo, b01)));
            acc23[pi] = __hadd2(acc23[pi], h2rcp(__hadd2(alo, b23)));
            uint2 b1 = *(const uint2*)&bp[(k0 + 1) * 16];
            __half2 c01 = *(__half2*)&b1.x, c23 = *(__half2*)&b1.y;
            acc01[pi + 1] = __hadd2(acc01[pi + 1], h2rcp(__hadd2(ahi, c01)));
            acc23[pi + 1] = __hadd2(acc23[pi + 1], h2rcp(__hadd2(ahi, c23)));
        }
    }

    float s0 = 0.f, s1 = 0.f, s2 = 0.f, s3 = 0.f;
#pragma unroll
    for (int i = 0; i < 8; i++) {
        float2 f01 = __half22float2(acc01[i]);
        float2 f23 = __half22float2(acc23[i]);
        s0 += f01.x; s1 += f01.y; s2 += f23.x; s3 += f23.y;
    }
    int slot = b * L + l;
    float* dst = ((slog & 1) ? g_buf1 : g_buf0) + (size_t)slot * MAT;
    *(float4*)&dst[row * D + q * 16 + cg * 4] =
        make_float4(frcp(s0), frcp(s1), frcp(s2), frcp(s3));
    if (t == 0 && q == 0)
        ((slog & 1) ? g_presc1 : g_presc0)[slot] = s;
}

// ---------------------------------------------------------------------------
// Final: x = init (x) PM ; y = x (x) p0 ; output in log domain. fp32 path.
// ---------------------------------------------------------------------------
__global__ void final_kernel(const int* __restrict__ act,
                             const float* __restrict__ init_vec,
                             float* __restrict__ out) {
    int bl = blockIdx.x;
    int b = bl >> 6, l = bl & 63;
    RMat W = latest_raw(act, b, l);
    __shared__ float ci[D];
    __shared__ float xw[D];
    int t = threadIdx.x;   // 64 threads
    ci[t] = expf(-init_vec[t]);
    __syncthreads();

    float s = 0.f;
#pragma unroll 8
    for (int k = 0; k < D; k++)
        s += frcp(fmaf(W.sc, W.m[k * D + t], ci[k]));
    xw[t] = frcp(s);
    __syncthreads();

    float s2 = 0.f;
#pragma unroll 8
    for (int k = 0; k < D; k++)
        s2 += frcp(xw[k] + g_p0tab[k * D + t]);
    out[(size_t)bl * D + t] = logf(s2);
}

extern "C" void kernel_launch(void* const* d_in, const int* in_sizes, int n_in,
                              void* d_out, int out_size) {
    const float* p        = (const float*)d_in[0];  // (5, 64, 64)
    const float* init_vec = (const float*)d_in[1];  // (64,)
    const int*   act      = (const int*)d_in[2];    // (8, 64)
    float* out = (float*)d_out;                     // (8, 64, 64)

    exp_tab_kernel<<<5, 256>>>(p);
    pair_kernel<<<64, 256>>>();
    stage2_kernel<<<1072, 256>>>(act);
    conv_init_kernel<<<280, 128>>>();
    hstep_kernel<<<8 * (L - 4) * 4, 256>>>(act, 2);    // -> buf0
    conv_pass_kernel<<<8 * (L - 4), 128>>>(2);
    hstep_kernel<<<8 * (L - 8) * 4, 256>>>(act, 3);    // -> buf1
    conv_pass_kernel<<<8 * (L - 8), 128>>>(3);
    hstep_kernel<<<8 * (L - 16) * 4, 256>>>(act, 4);   // -> buf0
    conv_pass_kernel<<<8 * (L - 16), 128>>>(4);
    hstep_kernel<<<8 * (L - 32) * 4, 256>>>(act, 5);   // -> buf1 (final reads raw)
    final_kernel<<<512, 64>>>(act, init_vec, out);
}

// round 9
// speedup vs baseline: 1.1894x; 1.0824x over previous
#include <cuda_runtime.h>
#include <cuda_fp16.h>

#define D 64
#define L 64
#define BB 8
#define MAT (D*D)          // 4096 elems per matrix
#define NMAT (BB*L)        // 512 matrices
#define PA 68              // fp32 A pitch (floats)
#define PAH 72             // fp16 A pitch (halves) -> 144B rows, conflict-free

// All matrices in reciprocal-exp domain: W = exp(-m), stored fp16 normalized
// per-quarter (max=1) with float scales. log-semiring matmul:
//   out[i,j] = rcp( sum_k rcp( A[i,k] + B[k,j] ) )   (scale-homogeneous)
__device__ float g_wtab[4 * MAT];      // exp(-p[a+1]) fp32 (pair_kernel input)
__device__ float g_ttab[16 * MAT];     // pair products fp32 (conv source)
__device__ float g_p0tab[MAT];         // exp(-p[0]) fp32 (final)

// fp16 normalized storage (+ per-quarter float4 scales)
__device__ uint4 h_buf0_[NMAT * MAT / 8];
__device__ uint4 h_buf1_[NMAT * MAT / 8];
__device__ uint4 h_qtab_[256 * MAT / 8];
__device__ uint4 h_ttab_[16 * MAT / 8];
__device__ uint4 h_wtab_[4 * MAT / 8];
__device__ float4 g_sc0[NMAT];
__device__ float4 g_sc1[NMAT];
__device__ float4 g_scq[256];
__device__ float4 g_sct[16];
__device__ float4 g_scw[4];
#define H_BUF0 ((__half*)h_buf0_)
#define H_BUF1 ((__half*)h_buf1_)
#define H_QTAB ((__half*)h_qtab_)
#define H_TTAB ((__half*)h_ttab_)
#define H_WTAB ((__half*)h_wtab_)

__device__ __forceinline__ float frcp(float x) {
    float r;
    asm("rcp.approx.f32 %0, %1;" : "=f"(r) : "f"(x));
    return r;
}

// ---------------------------------------------------------------------------
// fp32 quarter matmul (pair table only).
// ---------------------------------------------------------------------------
__device__ __forceinline__ void mm_quarter(const float* __restrict__ A,
                                           const float* __restrict__ B,
                                           float* __restrict__ Dst, int q) {
    __shared__ float sA[D * PA];
    __shared__ float sB[D * 16];
    const int t = threadIdx.x;
#pragma unroll
    for (int i = 0; i < 4; i++) {
        int idx = t + i * 256;
        int r = idx >> 4, c = idx & 15;
        *(float4*)&sA[r * PA + c * 4] = ((const float4*)A)[idx];
    }
    {
        int k = t >> 2, g = t & 3;
        *(float4*)&sB[k * 16 + g * 4] = *(const float4*)&B[k * D + q * 16 + g * 4];
    }
    __syncthreads();
    const int row = t >> 2, cg = t & 3;
    const float* ap = &sA[row * PA];
    const float* bp = &sB[cg * 4];
    float a0 = 0.f, a1 = 0.f, a2 = 0.f, a3 = 0.f;
#pragma unroll
    for (int k4 = 0; k4 < 16; k4++) {
        float4 av = *(const float4*)&ap[k4 * 4];
        float4 bA = *(const float4*)&bp[(k4 * 4 + 0) * 16];
        float4 bB = *(const float4*)&bp[(k4 * 4 + 1) * 16];
        float4 bC = *(const float4*)&bp[(k4 * 4 + 2) * 16];
        float4 bD = *(const float4*)&bp[(k4 * 4 + 3) * 16];
        a0 += frcp(av.x + bA.x); a1 += frcp(av.x + bA.y);
        a2 += frcp(av.x + bA.z); a3 += frcp(av.x + bA.w);
        a0 += frcp(av.y + bB.x); a1 += frcp(av.y + bB.y);
        a2 += frcp(av.y + bB.z); a3 += frcp(av.y + bB.w);
        a0 += frcp(av.z + bC.x); a1 += frcp(av.z + bC.y);
        a2 += frcp(av.z + bC.z); a3 += frcp(av.z + bC.w);
        a0 += frcp(av.w + bD.x); a1 += frcp(av.w + bD.y);
        a2 += frcp(av.w + bD.z); a3 += frcp(av.w + bD.w);
    }
    *(float4*)&Dst[row * D + q * 16 + cg * 4] =
        make_float4(frcp(a0), frcp(a1), frcp(a2), frcp(a3));
}

// ---------------------------------------------------------------------------
// fp16 quarter matmul with fused per-quarter normalization epilogue.
// One CTA = 64x16 output quarter q. scA = A's 4 quarter scales, scB = B's
// scale for quarter q. Writes normalized fp16 + scOut (the q-th scale slot).
// ---------------------------------------------------------------------------
__device__ __forceinline__ void hmm_quarter(const __half* __restrict__ Ah, float4 scA,
                                            const __half* __restrict__ Bh, float scB,
                                            __half* __restrict__ Dst,
                                            float* __restrict__ scOut, int q) {
    __shared__ __align__(16) __half sA[D * PAH];
    __shared__ __align__(16) __half sB[D * 16];
    __shared__ float wred[8];
    const int t = threadIdx.x;

    float s = fmaxf(fmaxf(fmaxf(scA.x, scA.y), fmaxf(scA.z, scA.w)), scB);
    float invs = 1.f / s;
    __half2 rB = __float2half2_rn(scB * invs);
    float rAf0 = scA.x * invs, rAf1 = scA.y * invs;
    float rAf2 = scA.z * invs, rAf3 = scA.w * invs;

    // stage A: 512 uint4 (8 halves each); quarter of columns = (c8>>1)
#pragma unroll
    for (int i = 0; i < 2; i++) {
        int id = t + i * 256;
        int r = id >> 3, c8 = id & 7;
        int qa = c8 >> 1;
        float rf = (qa < 2) ? (qa == 0 ? rAf0 : rAf1) : (qa == 2 ? rAf2 : rAf3);
        __half2 rA = __float2half2_rn(rf);
        uint4 v = ((const uint4*)Ah)[id];
        __half2* hv = (__half2*)&v;
        hv[0] = __hmul2(hv[0], rA); hv[1] = __hmul2(hv[1], rA);
        hv[2] = __hmul2(hv[2], rA); hv[3] = __hmul2(hv[3], rA);
        *(uint4*)&sA[r * PAH + c8 * 8] = v;
    }
    // stage B quarter: 128 uint4
    if (t < 128) {
        int r = t >> 1, c8 = t & 1;
        uint4 v = *(const uint4*)&Bh[r * D + q * 16 + c8 * 8];
        __half2* hv = (__half2*)&v;
        hv[0] = __hmul2(hv[0], rB); hv[1] = __hmul2(hv[1], rB);
        hv[2] = __hmul2(hv[2], rB); hv[3] = __hmul2(hv[3], rB);
        *(uint4*)&sB[r * 16 + c8 * 8] = v;
    }
    __syncthreads();

    const int row = t >> 2, cg = t & 3;
    const __half* ap = &sA[row * PAH];
    const __half* bp = &sB[cg * 4];
    const __half2 hz = __float2half2_rn(0.f);
    __half2 acc01[8], acc23[8];
#pragma unroll
    for (int i = 0; i < 8; i++) { acc01[i] = hz; acc23[i] = hz; }

#pragma unroll
    for (int k8 = 0; k8 < 8; k8++) {
        uint4 a8 = *(const uint4*)&ap[k8 * 8];
        const __half2* ah = (const __half2*)&a8;
#pragma unroll
        for (int kk = 0; kk < 4; kk++) {
            int k0 = k8 * 8 + kk * 2;
            __half2 alo = __low2half2(ah[kk]);
            __half2 ahi = __high2half2(ah[kk]);
            int pi = kk * 2;
            uint2 b0 = *(const uint2*)&bp[k0 * 16];
            __half2 b01 = *(__half2*)&b0.x, b23 = *(__half2*)&b0.y;
            acc01[pi] = __hadd2(acc01[pi], h2rcp(__hadd2(alo, b01)));
            acc23[pi] = __hadd2(acc23[pi], h2rcp(__hadd2(alo, b23)));
            uint2 b1 = *(const uint2*)&bp[(k0 + 1) * 16];
            __half2 c01 = *(__half2*)&b1.x, c23 = *(__half2*)&b1.y;
            acc01[pi + 1] = __hadd2(acc01[pi + 1], h2rcp(__hadd2(ahi, c01)));
            acc23[pi + 1] = __hadd2(acc23[pi + 1], h2rcp(__hadd2(ahi, c23)));
        }
    }

    float s0 = 0.f, s1 = 0.f, s2 = 0.f, s3 = 0.f;
#pragma unroll
    for (int i = 0; i < 8; i++) {
        float2 f01 = __half22float2(acc01[i]);
        float2 f23 = __half22float2(acc23[i]);
        s0 += f01.x; s1 += f01.y; s2 += f23.x; s3 += f23.y;
    }
    float o0 = frcp(s0), o1 = frcp(s1), o2 = frcp(s2), o3 = frcp(s3);

    // fused per-quarter max reduction + normalized fp16 store
    float m = fmaxf(fmaxf(o0, o1), fmaxf(o2, o3));
#pragma unroll
    for (int off = 16; off; off >>= 1)
        m = fmaxf(m, __shfl_xor_sync(0xffffffffu, m, off));
    if ((t & 31) == 0) wred[t >> 5] = m;
    __syncthreads();
    float mx = wred[0];
#pragma unroll
    for (int i = 1; i < 8; i++) mx = fmaxf(mx, wred[i]);
    float inv = (mx > 0.f) ? frcp(mx) : 0.f;

    __half2 h0 = __floats2half2_rn(o0 * inv, o1 * inv);
    __half2 h1 = __floats2half2_rn(o2 * inv, o3 * inv);
    uint2 u;
    u.x = *(unsigned*)&h0;
    u.y = *(unsigned*)&h1;
    *(uint2*)&Dst[row * D + q * 16 + cg * 4] = u;
    if (t == 0) *scOut = s * mx;
}

// ---------------------------------------------------------------------------
// Resolver: value of index m before pass 2^slog lives at level
// p = min(floor(log2 m), slog-1).
// ---------------------------------------------------------------------------
struct HMat { const __half* m; float4 sc; };

__device__ __forceinline__ int quad_idx(const int* __restrict__ act, int b, int m) {
    const int* a = act + b * L + (m - 3);
    return ((a[0] * 4 + a[1]) * 4 + a[2]) * 4 + a[3];
}

__device__ __forceinline__ HMat latest_h(const int* __restrict__ act,
                                         int b, int m, int slog) {
    int slot = b * L + m;
    size_t off = (size_t)slot * MAT;
    HMat r;
    if (m < 2) { r.m = H_BUF0 + off; r.sc = g_sc0[slot]; return r; }
    int p = 31 - __clz(m);
    if (p > slog - 1) p = slog - 1;
    if (p == 1) {
        if (m == 2) { r.m = H_BUF1 + off; r.sc = g_sc1[slot]; return r; }
        int idx = quad_idx(act, b, m);
        r.m = H_QTAB + (size_t)idx * MAT; r.sc = g_scq[idx]; return r;
    }
    if (p & 1) { r.m = H_BUF1 + off; r.sc = g_sc1[slot]; }
    else       { r.m = H_BUF0 + off; r.sc = g_sc0[slot]; }
    return r;
}

__device__ __forceinline__ float sc_comp(float4 s, int q) {
    return (q < 2) ? (q == 0 ? s.x : s.y) : (q == 2 ? s.z : s.w);
}

// ---------------------------------------------------------------------------
// exp tables: a==0 -> p0tab fp32. a>=1 -> wtab fp32 + fp16 normalized + scale.
// ---------------------------------------------------------------------------
__global__ void exp_tab_kernel(const float* __restrict__ p) {
    int a = blockIdx.x;
    __shared__ float wred[8];
    int t = threadIdx.x;  // 256
    const float4* src = (const float4*)(p + (size_t)a * MAT);
    float4 v[4];
    float m = 0.f;
#pragma unroll
    for (int i = 0; i < 4; i++) {
        float4 x = src[t + i * 256];
        v[i] = make_float4(expf(-x.x), expf(-x.y), expf(-x.z), expf(-x.w));
        m = fmaxf(m, fmaxf(fmaxf(v[i].x, v[i].y), fmaxf(v[i].z, v[i].w)));
    }
    if (a == 0) {
#pragma unroll
        for (int i = 0; i < 4; i++) ((float4*)g_p0tab)[t + i * 256] = v[i];
        return;
    }
    float4* wdst = (float4*)(g_wtab + (size_t)(a - 1) * MAT);
#pragma unroll
    for (int i = 0; i < 4; i++) wdst[t + i * 256] = v[i];
#pragma unroll
    for (int off = 16; off; off >>= 1)
        m = fmaxf(m, __shfl_xor_sync(0xffffffffu, m, off));
    if ((t & 31) == 0) wred[t >> 5] = m;
    __syncthreads();
    float mx = wred[0];
#pragma unroll
    for (int i = 1; i < 8; i++) mx = fmaxf(mx, wred[i]);
    float inv = (mx > 0.f) ? 1.f / mx : 0.f;
    __half* hdst = H_WTAB + (size_t)(a - 1) * MAT;
#pragma unroll
    for (int i = 0; i < 4; i++) {
        __half2 h0 = __floats2half2_rn(v[i].x * inv, v[i].y * inv);
        __half2 h1 = __floats2half2_rn(v[i].z * inv, v[i].w * inv);
        uint2 u; u.x = *(unsigned*)&h0; u.y = *(unsigned*)&h1;
        ((uint2*)hdst)[t + i * 256] = u;
    }
    if (t == 0) g_scw[a - 1] = make_float4(mx, mx, mx, mx);
}

// pair products (fp32): 16 pairs x 4 quarters = 64 CTAs
__global__ void __launch_bounds__(256, 5) pair_kernel() {
    int pidx = blockIdx.x >> 2, q = blockIdx.x & 3;
    int a = pidx >> 2, b = pidx & 3;
    mm_quarter(g_wtab + (size_t)a * MAT, g_wtab + (size_t)b * MAT,
               g_ttab + (size_t)pidx * MAT, q);
}

// convert ttab fp32 -> fp16 normalized (16 CTAs x 256)
__global__ void conv_tt_kernel() {
    int i = blockIdx.x;
    __shared__ float wred[8];
    int t = threadIdx.x;
    const float4* src = (const float4*)(g_ttab + (size_t)i * MAT);
    float4 v[4];
    float m = 0.f;
#pragma unroll
    for (int j = 0; j < 4; j++) {
        v[j] = src[t + j * 256];
        m = fmaxf(m, fmaxf(fmaxf(v[j].x, v[j].y), fmaxf(v[j].z, v[j].w)));
    }
#pragma unroll
    for (int off = 16; off; off >>= 1)
        m = fmaxf(m, __shfl_xor_sync(0xffffffffu, m, off));
    if ((t & 31) == 0) wred[t >> 5] = m;
    __syncthreads();
    float mx = wred[0];
#pragma unroll
    for (int j = 1; j < 8; j++) mx = fmaxf(mx, wred[j]);
    float inv = (mx > 0.f) ? 1.f / mx : 0.f;
    __half* hdst = H_TTAB + (size_t)i * MAT;
#pragma unroll
    for (int j = 0; j < 4; j++) {
        __half2 h0 = __floats2half2_rn(v[j].x * inv, v[j].y * inv);
        __half2 h1 = __floats2half2_rn(v[j].z * inv, v[j].w * inv);
        uint2 u; u.x = *(unsigned*)&h0; u.y = *(unsigned*)&h1;
        ((uint2*)hdst)[t + j * 256] = u;
    }
    if (t == 0) g_sct[i] = make_float4(mx, mx, mx, mx);
}

// quads (1024) + tris (32) + base fp16 copies l=0,1 (16) = 1072 CTAs
__global__ void __launch_bounds__(256, 5) stage2h_kernel(const int* __restrict__ act) {
    int bid = blockIdx.x;
    if (bid < 1024) {
        int qidx = bid >> 2, q = bid & 3;
        int hi = qidx >> 4, lo = qidx & 15;
        hmm_quarter(H_TTAB + (size_t)hi * MAT, g_sct[hi],
                    H_TTAB + (size_t)lo * MAT, sc_comp(g_sct[lo], q),
                    H_QTAB + (size_t)qidx * MAT, (float*)&g_scq[qidx] + q, q);
    } else if (bid < 1056) {
        int i = bid - 1024;
        int b = i >> 2, q = i & 3;
        int a0 = act[b * L], a12 = act[b * L + 1] * 4 + act[b * L + 2];
        int slot = b * L + 2;
        hmm_quarter(H_WTAB + (size_t)a0 * MAT, g_scw[a0],
                    H_TTAB + (size_t)a12 * MAT, sc_comp(g_sct[a12], q),
                    H_BUF1 + (size_t)slot * MAT, (float*)&g_sc1[slot] + q, q);
    } else {
        int i = bid - 1056;                 // 0..15
        int b = i >> 1, which = i & 1;      // l = 0 or 1
        int slot = b * L + which;
        const uint4* src;
        float4 sc;
        if (which) {
            int pidx = act[b * L] * 4 + act[b * L + 1];
            src = (const uint4*)(H_TTAB + (size_t)pidx * MAT);
            sc = g_sct[pidx];
        } else {
            int a0 = act[b * L];
            src = (const uint4*)(H_WTAB + (size_t)a0 * MAT);
            sc = g_scw[a0];
        }
        uint4* dst = (uint4*)(H_BUF0 + (size_t)slot * MAT);
        for (int j = threadIdx.x; j < MAT / 8; j += 256) dst[j] = src[j];
        if (threadIdx.x == 0) g_sc0[slot] = sc;
    }
}

// Doubling pass for step = 2^slog (slog >= 2). Fully fp16, fused normalize.
__global__ void __launch_bounds__(256, 5) hstep_kernel(const int* __restrict__ act,
                                                       int slog) {
    int step = 1 << slog, n = L - step;
    int idx = blockIdx.x >> 2, q = blockIdx.x & 3;
    int b = idx / n;
    int l = step + (idx - b * n);
    HMat A = latest_h(act, b, l - step, slog);
    HMat Bm = latest_h(act, b, l, slog);
    int slot = b * L + l;
    __half* dst = ((slog & 1) ? H_BUF1 : H_BUF0) + (size_t)slot * MAT;
    float* scarr = (float*)(((slog & 1) ? g_sc1 : g_sc0) + slot) + q;
    hmm_quarter(A.m, A.sc, Bm.m, sc_comp(Bm.sc, q), dst, scarr, q);
}

// Final: x = init (x) PM ; y = x (x) p0 ; output in log domain.
__global__ void final_kernel(const int* __restrict__ act,
                             const float* __restrict__ init_vec,
                             float* __restrict__ out) {
    int bl = blockIdx.x;
    int b = bl >> 6, l = bl & 63;
    HMat W = latest_h(act, b, l, 6);
    __shared__ float ci[D];
    __shared__ float xw[D];
    int t = threadIdx.x;   // 64
    ci[t] = expf(-init_vec[t]);
    __syncthreads();

    float scq = sc_comp(W.sc, t >> 4);
    float s = 0.f;
#pragma unroll 8
    for (int k = 0; k < D; k++)
        s += frcp(fmaf(scq, __half2float(W.m[k * D + t]), ci[k]));
    xw[t] = frcp(s);
    __syncthreads();

    float s2 = 0.f;
#pragma unroll 8
    for (int k = 0; k < D; k++)
        s2 += frcp(xw[k] + g_p0tab[k * D + t]);
    out[(size_t)bl * D + t] = logf(s2);
}

extern "C" void kernel_launch(void* const* d_in, const int* in_sizes, int n_in,
                              void* d_out, int out_size) {
    const float* p        = (const float*)d_in[0];  // (5, 64, 64)
    const float* init_vec = (const float*)d_in[1];  // (64,)
    const int*   act      = (const int*)d_in[2];    // (8, 64)
    float* out = (float*)d_out;                     // (8, 64, 64)

    exp_tab_kernel<<<5, 256>>>(p);
    pair_kernel<<<64, 256>>>();
    conv_tt_kernel<<<16, 256>>>();
    stage2h_kernel<<<1072, 256>>>(act);
    hstep_kernel<<<8 * (L - 4)  * 4, 256>>>(act, 2);   // -> H_BUF0
    hstep_kernel<<<8 * (L - 8)  * 4, 256>>>(act, 3);   // -> H_BUF1
    hstep_kernel<<<8 * (L - 16) * 4, 256>>>(act, 4);   // -> H_BUF0
    hstep_kernel<<<8 * (L - 32) * 4, 256>>>(act, 5);   // -> H_BUF1
    final_kernel<<<512, 64>>>(act, init_vec, out);
}

// round 10
// speedup vs baseline: 1.2054x; 1.0134x over previous
#include <cuda_runtime.h>
#include <cuda_fp16.h>

#define D 64
#define L 64
#define BB 8
#define MAT (D*D)          // 4096 elems per matrix
#define NMAT (BB*L)        // 512 matrices
#define PAH 72             // fp16 A pitch (halves) -> 144B rows, conflict-free

// All matrices in reciprocal-exp domain: W = exp(-m), stored fp16 normalized
// per-quarter (max=1) with float scales. log-semiring matmul:
//   out[i,j] = rcp( sum_k rcp( A[i,k] + B[k,j] ) )   (scale-homogeneous)
__device__ float g_p0tab[MAT];         // exp(-p[0]) fp32 (final)

// fp16 normalized storage (+ per-quarter float4 scales)
__device__ uint4 h_buf0_[NMAT * MAT / 8];
__device__ uint4 h_buf1_[NMAT * MAT / 8];
__device__ uint4 h_qtab_[256 * MAT / 8];
__device__ uint4 h_ttab_[16 * MAT / 8];
__device__ uint4 h_wtab_[4 * MAT / 8];
__device__ float4 g_sc0[NMAT];
__device__ float4 g_sc1[NMAT];
__device__ float4 g_scq[256];
__device__ float4 g_sct[16];
__device__ float4 g_scw[4];
#define H_BUF0 ((__half*)h_buf0_)
#define H_BUF1 ((__half*)h_buf1_)
#define H_QTAB ((__half*)h_qtab_)
#define H_TTAB ((__half*)h_ttab_)
#define H_WTAB ((__half*)h_wtab_)

__device__ __forceinline__ float frcp(float x) {
    float r;
    asm("rcp.approx.f32 %0, %1;" : "=f"(r) : "f"(x));
    return r;
}

__device__ __forceinline__ float sc_comp(float4 s, int q) {
    return (q < 2) ? (q == 0 ? s.x : s.y) : (q == 2 ? s.z : s.w);
}

// ---------------------------------------------------------------------------
// fp16 quarter matmul with fused per-quarter normalization epilogue.
// One CTA = 64x16 output quarter q. scA = A's 4 quarter scales, scB = B's
// scale for quarter q. Writes normalized fp16 + scOut (the q-th scale slot).
// ---------------------------------------------------------------------------
__device__ __forceinline__ void hmm_quarter(const __half* __restrict__ Ah, float4 scA,
                                            const __half* __restrict__ Bh, float scB,
                                            __half* __restrict__ Dst,
                                            float* __restrict__ scOut, int q) {
    __shared__ __align__(16) __half sA[D * PAH];
    __shared__ __align__(16) __half sB[D * 16];
    __shared__ float wred[8];
    const int t = threadIdx.x;

    float s = fmaxf(fmaxf(fmaxf(scA.x, scA.y), fmaxf(scA.z, scA.w)), scB);
    float invs = 1.f / s;
    __half2 rB = __float2half2_rn(scB * invs);
    float rAf0 = scA.x * invs, rAf1 = scA.y * invs;
    float rAf2 = scA.z * invs, rAf3 = scA.w * invs;

    // stage A: 512 uint4 (8 halves each); quarter of columns = (c8>>1)
#pragma unroll
    for (int i = 0; i < 2; i++) {
        int id = t + i * 256;
        int r = id >> 3, c8 = id & 7;
        int qa = c8 >> 1;
        float rf = (qa < 2) ? (qa == 0 ? rAf0 : rAf1) : (qa == 2 ? rAf2 : rAf3);
        __half2 rA = __float2half2_rn(rf);
        uint4 v = ((const uint4*)Ah)[id];
        __half2* hv = (__half2*)&v;
        hv[0] = __hmul2(hv[0], rA); hv[1] = __hmul2(hv[1], rA);
        hv[2] = __hmul2(hv[2], rA); hv[3] = __hmul2(hv[3], rA);
        *(uint4*)&sA[r * PAH + c8 * 8] = v;
    }
    // stage B quarter: 128 uint4
    if (t < 128) {
        int r = t >> 1, c8 = t & 1;
        uint4 v = *(const uint4*)&Bh[r * D + q * 16 + c8 * 8];
        __half2* hv = (__half2*)&v;
        hv[0] = __hmul2(hv[0], rB); hv[1] = __hmul2(hv[1], rB);
        hv[2] = __hmul2(hv[2], rB); hv[3] = __hmul2(hv[3], rB);
        *(uint4*)&sB[r * 16 + c8 * 8] = v;
    }
    __syncthreads();

    const int row = t >> 2, cg = t & 3;
    const __half* ap = &sA[row * PAH];
    const __half* bp = &sB[cg * 4];
    const __half2 hz = __float2half2_rn(0.f);
    __half2 acc01[8], acc23[8];
#pragma unroll
    for (int i = 0; i < 8; i++) { acc01[i] = hz; acc23[i] = hz; }

#pragma unroll
    for (int k8 = 0; k8 < 8; k8++) {
        uint4 a8 = *(const uint4*)&ap[k8 * 8];
        const __half2* ah = (const __half2*)&a8;
#pragma unroll
        for (int kk = 0; kk < 4; kk++) {
            int k0 = k8 * 8 + kk * 2;
            __half2 alo = __low2half2(ah[kk]);
            __half2 ahi = __high2half2(ah[kk]);
            int pi = kk * 2;
            uint2 b0 = *(const uint2*)&bp[k0 * 16];
            __half2 b01 = *(__half2*)&b0.x, b23 = *(__half2*)&b0.y;
            acc01[pi] = __hadd2(acc01[pi], h2rcp(__hadd2(alo, b01)));
            acc23[pi] = __hadd2(acc23[pi], h2rcp(__hadd2(alo, b23)));
            uint2 b1 = *(const uint2*)&bp[(k0 + 1) * 16];
            __half2 c01 = *(__half2*)&b1.x, c23 = *(__half2*)&b1.y;
            acc01[pi + 1] = __hadd2(acc01[pi + 1], h2rcp(__hadd2(ahi, c01)));
            acc23[pi + 1] = __hadd2(acc23[pi + 1], h2rcp(__hadd2(ahi, c23)));
        }
    }

    float s0 = 0.f, s1 = 0.f, s2 = 0.f, s3 = 0.f;
#pragma unroll
    for (int i = 0; i < 8; i++) {
        float2 f01 = __half22float2(acc01[i]);
        float2 f23 = __half22float2(acc23[i]);
        s0 += f01.x; s1 += f01.y; s2 += f23.x; s3 += f23.y;
    }
    float o0 = frcp(s0), o1 = frcp(s1), o2 = frcp(s2), o3 = frcp(s3);

    // fused per-quarter max reduction + normalized fp16 store
    float m = fmaxf(fmaxf(o0, o1), fmaxf(o2, o3));
#pragma unroll
    for (int off = 16; off; off >>= 1)
        m = fmaxf(m, __shfl_xor_sync(0xffffffffu, m, off));
    if ((t & 31) == 0) wred[t >> 5] = m;
    __syncthreads();
    float mx = wred[0];
#pragma unroll
    for (int i = 1; i < 8; i++) mx = fmaxf(mx, wred[i]);
    float inv = (mx > 0.f) ? frcp(mx) : 0.f;

    __half2 h0 = __floats2half2_rn(o0 * inv, o1 * inv);
    __half2 h1 = __floats2half2_rn(o2 * inv, o3 * inv);
    uint2 u;
    u.x = *(unsigned*)&h0;
    u.y = *(unsigned*)&h1;
    *(uint2*)&Dst[row * D + q * 16 + cg * 4] = u;
    if (t == 0) *scOut = s * mx;
}

// ---------------------------------------------------------------------------
// Resolver: value of index m before pass 2^slog lives at level
// p = min(floor(log2 m), slog-1).
// ---------------------------------------------------------------------------
struct HMat { const __half* m; float4 sc; };

__device__ __forceinline__ int quad_idx(const int* __restrict__ act, int b, int m) {
    const int* a = act + b * L + (m - 3);
    return ((a[0] * 4 + a[1]) * 4 + a[2]) * 4 + a[3];
}

__device__ __forceinline__ HMat latest_h(const int* __restrict__ act,
                                         int b, int m, int slog) {
    int slot = b * L + m;
    size_t off = (size_t)slot * MAT;
    HMat r;
    if (m < 2) { r.m = H_BUF0 + off; r.sc = g_sc0[slot]; return r; }
    int p = 31 - __clz(m);
    if (p > slog - 1) p = slog - 1;
    if (p == 1) {
        if (m == 2) { r.m = H_BUF1 + off; r.sc = g_sc1[slot]; return r; }
        int idx = quad_idx(act, b, m);
        r.m = H_QTAB + (size_t)idx * MAT; r.sc = g_scq[idx]; return r;
    }
    if (p & 1) { r.m = H_BUF1 + off; r.sc = g_sc1[slot]; }
    else       { r.m = H_BUF0 + off; r.sc = g_sc0[slot]; }
    return r;
}

// ---------------------------------------------------------------------------
// exp tables: a==0 -> p0tab fp32. a>=1 -> wtab fp16 normalized + scale.
// ---------------------------------------------------------------------------
__global__ void exp_tab_kernel(const float* __restrict__ p) {
    int a = blockIdx.x;
    __shared__ float wred[8];
    int t = threadIdx.x;  // 256
    const float4* src = (const float4*)(p + (size_t)a * MAT);
    float4 v[4];
    float m = 0.f;
#pragma unroll
    for (int i = 0; i < 4; i++) {
        float4 x = src[t + i * 256];
        v[i] = make_float4(expf(-x.x), expf(-x.y), expf(-x.z), expf(-x.w));
        m = fmaxf(m, fmaxf(fmaxf(v[i].x, v[i].y), fmaxf(v[i].z, v[i].w)));
    }
    if (a == 0) {
#pragma unroll
        for (int i = 0; i < 4; i++) ((float4*)g_p0tab)[t + i * 256] = v[i];
        return;
    }
#pragma unroll
    for (int off = 16; off; off >>= 1)
        m = fmaxf(m, __shfl_xor_sync(0xffffffffu, m, off));
    if ((t & 31) == 0) wred[t >> 5] = m;
    __syncthreads();
    float mx = wred[0];
#pragma unroll
    for (int i = 1; i < 8; i++) mx = fmaxf(mx, wred[i]);
    float inv = (mx > 0.f) ? 1.f / mx : 0.f;
    __half* hdst = H_WTAB + (size_t)(a - 1) * MAT;
#pragma unroll
    for (int i = 0; i < 4; i++) {
        __half2 h0 = __floats2half2_rn(v[i].x * inv, v[i].y * inv);
        __half2 h1 = __floats2half2_rn(v[i].z * inv, v[i].w * inv);
        uint2 u; u.x = *(unsigned*)&h0; u.y = *(unsigned*)&h1;
        ((uint2*)hdst)[t + i * 256] = u;
    }
    if (t == 0) g_scw[a - 1] = make_float4(mx, mx, mx, mx);
}

// pair products fp16: 16 pairs x 4 quarters = 64 CTAs
__global__ void __launch_bounds__(256, 6) pairh_kernel() {
    int pidx = blockIdx.x >> 2, q = blockIdx.x & 3;
    int a = pidx >> 2, b = pidx & 3;
    hmm_quarter(H_WTAB + (size_t)a * MAT, g_scw[a],
                H_WTAB + (size_t)b * MAT, sc_comp(g_scw[b], q),
                H_TTAB + (size_t)pidx * MAT, (float*)&g_sct[pidx] + q, q);
}

// quads (1024) + tris (32) + base fp16 copies l=0,1 (16) = 1072 CTAs
__global__ void __launch_bounds__(256, 6) stage2h_kernel(const int* __restrict__ act) {
    int bid = blockIdx.x;
    if (bid < 1024) {
        int qidx = bid >> 2, q = bid & 3;
        int hi = qidx >> 4, lo = qidx & 15;
        hmm_quarter(H_TTAB + (size_t)hi * MAT, g_sct[hi],
                    H_TTAB + (size_t)lo * MAT, sc_comp(g_sct[lo], q),
                    H_QTAB + (size_t)qidx * MAT, (float*)&g_scq[qidx] + q, q);
    } else if (bid < 1056) {
        int i = bid - 1024;
        int b = i >> 2, q = i & 3;
        int a0 = act[b * L], a12 = act[b * L + 1] * 4 + act[b * L + 2];
        int slot = b * L + 2;
        hmm_quarter(H_WTAB + (size_t)a0 * MAT, g_scw[a0],
                    H_TTAB + (size_t)a12 * MAT, sc_comp(g_sct[a12], q),
                    H_BUF1 + (size_t)slot * MAT, (float*)&g_sc1[slot] + q, q);
    } else {
        int i = bid - 1056;                 // 0..15
        int b = i >> 1, which = i & 1;      // l = 0 or 1
        int slot = b * L + which;
        const uint4* src;
        float4 sc;
        if (which) {
            int pidx = act[b * L] * 4 + act[b * L + 1];
            src = (const uint4*)(H_TTAB + (size_t)pidx * MAT);
            sc = g_sct[pidx];
        } else {
            int a0 = act[b * L];
            src = (const uint4*)(H_WTAB + (size_t)a0 * MAT);
            sc = g_scw[a0];
        }
        uint4* dst = (uint4*)(H_BUF0 + (size_t)slot * MAT);
        for (int j = threadIdx.x; j < MAT / 8; j += 256) dst[j] = src[j];
        if (threadIdx.x == 0) g_sc0[slot] = sc;
    }
}

// Doubling pass for step = 2^slog (slog >= 2). Fully fp16, fused normalize.
__global__ void __launch_bounds__(256, 6) hstep_kernel(const int* __restrict__ act,
                                                       int slog) {
    int step = 1 << slog, n = L - step;
    int idx = blockIdx.x >> 2, q = blockIdx.x & 3;
    int b = idx / n;
    int l = step + (idx - b * n);
    HMat A = latest_h(act, b, l - step, slog);
    HMat Bm = latest_h(act, b, l, slog);
    int slot = b * L + l;
    __half* dst = ((slog & 1) ? H_BUF1 : H_BUF0) + (size_t)slot * MAT;
    float* scarr = (float*)(((slog & 1) ? g_sc1 : g_sc0) + slot) + q;
    hmm_quarter(A.m, A.sc, Bm.m, sc_comp(Bm.sc, q), dst, scarr, q);
}

// Final: x = init (x) PM ; y = x (x) p0 ; output in log domain.
__global__ void final_kernel(const int* __restrict__ act,
                             const float* __restrict__ init_vec,
                             float* __restrict__ out) {
    int bl = blockIdx.x;
    int b = bl >> 6, l = bl & 63;
    HMat W = latest_h(act, b, l, 6);
    __shared__ float ci[D];
    __shared__ float xw[D];
    int t = threadIdx.x;   // 64
    ci[t] = expf(-init_vec[t]);
    __syncthreads();

    float scq = sc_comp(W.sc, t >> 4);
    float s = 0.f;
#pragma unroll 8
    for (int k = 0; k < D; k++)
        s += frcp(fmaf(scq, __half2float(W.m[k * D + t]), ci[k]));
    xw[t] = frcp(s);
    __syncthreads();

    float s2 = 0.f;
#pragma unroll 8
    for (int k = 0; k < D; k++)
        s2 += frcp(xw[k] + g_p0tab[k * D + t]);
    out[(size_t)bl * D + t] = logf(s2);
}

extern "C" void kernel_launch(void* const* d_in, const int* in_sizes, int n_in,
                              void* d_out, int out_size) {
    const float* p        = (const float*)d_in[0];  // (5, 64, 64)
    const float* init_vec = (const float*)d_in[1];  // (64,)
    const int*   act      = (const int*)d_in[2];    // (8, 64)
    float* out = (float*)d_out;                     // (8, 64, 64)

    exp_tab_kernel<<<5, 256>>>(p);
    pairh_kernel<<<64, 256>>>();
    stage2h_kernel<<<1072, 256>>>(act);
    hstep_kernel<<<8 * (L - 4)  * 4, 256>>>(act, 2);   // -> H_BUF0
    hstep_kernel<<<8 * (L - 8)  * 4, 256>>>(act, 3);   // -> H_BUF1
    hstep_kernel<<<8 * (L - 16) * 4, 256>>>(act, 4);   // -> H_BUF0
    hstep_kernel<<<8 * (L - 32) * 4, 256>>>(act, 5);   // -> H_BUF1
    final_kernel<<<512, 64>>>(act, init_vec, out);
}